// round 3
// baseline (speedup 1.0000x reference)
#include <cuda_runtime.h>

#define DIM    256
#define NE     8192
#define NROWS  32768

#define BM 32
#define BN 128
#define BK 16
#define XST 36   // padded row stride (floats) for xT tile; 36*4=144B, 16B-aligned

// ---- device scratch (no allocations allowed) ----
__device__ float  g_c[NE];            // 0.5 * ||e_j||^2
__device__ int    g_idx[NROWS];       // argmin index per row
__device__ float  g_eT[NE * DIM];     // transposed codebook [j][d] (32 MB)
__device__ double g_diff;             // commitment loss accumulator

// ============================================================
// Kernel 1: half-norms of codebook columns + zero diff accum.
// ============================================================
__global__ void norms_kernel(const float* __restrict__ embed) {
    int j = blockIdx.x * blockDim.x + threadIdx.x;
    if (blockIdx.x == 0 && threadIdx.x == 0) g_diff = 0.0;
    if (j < NE) {
        float s = 0.f;
        #pragma unroll 8
        for (int d = 0; d < DIM; ++d) {
            float v = embed[(size_t)d * NE + j];
            s += v * v;
        }
        g_c[j] = 0.5f * s;
    }
}

// ============================================================
// Kernel 2: transpose embed [DIM][NE] -> g_eT [NE][DIM]
// ============================================================
__global__ void transpose_kernel(const float* __restrict__ embed) {
    __shared__ float t[32][33];
    int j0 = blockIdx.x * 32;
    int d0 = blockIdx.y * 32;
    int tx = threadIdx.x, ty = threadIdx.y;   // 32 x 8
    #pragma unroll
    for (int i = 0; i < 32; i += 8)
        t[ty + i][tx] = embed[(size_t)(d0 + ty + i) * NE + (j0 + tx)];
    __syncthreads();
    #pragma unroll
    for (int i = 0; i < 32; i += 8)
        g_eT[(size_t)(j0 + ty + i) * DIM + (d0 + tx)] = t[tx][ty + i];
}

// ============================================================
// Kernel 3: argmax over j of (x.e_j - 0.5||e_j||^2).
// STATIC shared memory only (44KB < 48KB): no opt-in attribute needed.
// Block: 32 rows x 8192 codes. 256 threads, 4x4 per-thread tile.
// ============================================================
__global__ void argmin_kernel(const float* __restrict__ input,
                              const float* __restrict__ embed) {
    __shared__ float xT[DIM * XST];   // 36864 B  : xT[k][r], r in 0..31
    __shared__ float es[BK * BN];     //  8192 B  : es[k][c], c in 0..127

    const int tid = threadIdx.x;
    const int rg  = tid >> 5;    // warp id 0..7 -> rows rg*4 .. rg*4+3
    const int cg  = tid & 31;    // lane -> codes cg*4 .. cg*4+3 within tile
    const int row0 = blockIdx.x * BM;

    // ---- load x tile transposed: input[row0+r][k] -> xT[k][r] ----
    {
        const float4* in4 = reinterpret_cast<const float4*>(input + (size_t)row0 * DIM);
        #pragma unroll
        for (int it = 0; it < 8; ++it) {
            int idx = tid + it * 256;     // 0..2047 = 32 rows x 64 float4
            int c4  = idx & 63;
            int r   = idx >> 6;
            float4 v = in4[r * 64 + c4];
            int k = c4 * 4;
            xT[(k + 0) * XST + r] = v.x;
            xT[(k + 1) * XST + r] = v.y;
            xT[(k + 2) * XST + r] = v.z;
            xT[(k + 3) * XST + r] = v.w;
        }
    }

    float bestv[4];
    int   besti[4];
    #pragma unroll
    for (int i = 0; i < 4; ++i) { bestv[i] = -3.0e38f; besti[i] = 0; }

    for (int jt = 0; jt < NE / BN; ++jt) {
        float acc[4][4];
        #pragma unroll
        for (int i = 0; i < 4; ++i)
            #pragma unroll
            for (int c = 0; c < 4; ++c) acc[i][c] = 0.f;

        #pragma unroll 1
        for (int kt = 0; kt < DIM / BK; ++kt) {
            __syncthreads();
            // load e tile [16][128]: 512 float4, 2 per thread, coalesced
            const float4* e4  = reinterpret_cast<const float4*>(
                embed + (size_t)(kt * BK) * NE + (size_t)jt * BN);
            float4* es4 = reinterpret_cast<float4*>(es);
            #pragma unroll
            for (int it = 0; it < 2; ++it) {
                int t  = tid + it * 256;      // 0..511
                int kk = t >> 5;              // 0..15
                int cc = t & 31;              // 0..31
                es4[kk * 32 + cc] = e4[(size_t)kk * (NE / 4) + cc];
            }
            __syncthreads();

            #pragma unroll
            for (int k = 0; k < BK; ++k) {
                // broadcast read: whole warp reads same 16B
                float4 xa = *reinterpret_cast<const float4*>(
                    xT + (kt * BK + k) * XST + rg * 4);
                float4 ev = reinterpret_cast<const float4*>(es + k * BN)[cg];

                acc[0][0] += xa.x * ev.x; acc[0][1] += xa.x * ev.y; acc[0][2] += xa.x * ev.z; acc[0][3] += xa.x * ev.w;
                acc[1][0] += xa.y * ev.x; acc[1][1] += xa.y * ev.y; acc[1][2] += xa.y * ev.z; acc[1][3] += xa.y * ev.w;
                acc[2][0] += xa.z * ev.x; acc[2][1] += xa.z * ev.y; acc[2][2] += xa.z * ev.z; acc[2][3] += xa.z * ev.w;
                acc[3][0] += xa.w * ev.x; acc[3][1] += xa.w * ev.y; acc[3][2] += xa.w * ev.z; acc[3][3] += xa.w * ev.w;
            }
        }

        // apply -0.5||e||^2 and update running best (ascending j -> first wins ties)
        int jbase = jt * BN + cg * 4;
        float c0 = g_c[jbase + 0];
        float c1 = g_c[jbase + 1];
        float c2 = g_c[jbase + 2];
        float c3 = g_c[jbase + 3];
        #pragma unroll
        for (int i = 0; i < 4; ++i) {
            float v0 = acc[i][0] - c0;
            float v1 = acc[i][1] - c1;
            float v2 = acc[i][2] - c2;
            float v3 = acc[i][3] - c3;
            if (v0 > bestv[i]) { bestv[i] = v0; besti[i] = jbase + 0; }
            if (v1 > bestv[i]) { bestv[i] = v1; besti[i] = jbase + 1; }
            if (v2 > bestv[i]) { bestv[i] = v2; besti[i] = jbase + 2; }
            if (v3 > bestv[i]) { bestv[i] = v3; besti[i] = jbase + 3; }
        }
    }

    // ---- cross-lane reduction per row (reuse es: 32*32 floats + 32*32 ints = 8KB) ----
    __syncthreads();
    float* rv = es;                                   // rv[c][r] = lane c best for row r
    int*   ri = reinterpret_cast<int*>(es + 32 * BM);
    #pragma unroll
    for (int i = 0; i < 4; ++i) {
        int r = rg * 4 + i;
        rv[cg * BM + r] = bestv[i];
        ri[cg * BM + r] = besti[i];
    }
    __syncthreads();
    if (tid < BM) {
        float bv = rv[tid];      // lane 0
        int   bi = ri[tid];
        #pragma unroll 4
        for (int c = 1; c < 32; ++c) {
            float v = rv[c * BM + tid];
            int   x = ri[c * BM + tid];
            if (v > bv || (v == bv && x < bi)) { bv = v; bi = x; }
        }
        g_idx[row0 + tid] = bi;
    }
}

// ============================================================
// Kernel 4: gather quantize, elementwise commitment loss, index out.
// ============================================================
__global__ void output_kernel(const float* __restrict__ input,
                              float* __restrict__ out, int write_extra) {
    int row  = blockIdx.x * 8 + (threadIdx.x >> 5);
    int lane = threadIdx.x & 31;
    int j = g_idx[row];
    const float4* x4 = reinterpret_cast<const float4*>(input + (size_t)row * DIM);
    const float4* e4 = reinterpret_cast<const float4*>(g_eT + (size_t)j * DIM);
    float4*       q4 = reinterpret_cast<float4*>(out + (size_t)row * DIM);
    float s = 0.f;
    #pragma unroll
    for (int t = 0; t < 2; ++t) {
        int d4 = lane + t * 32;
        float4 e = e4[d4];
        float4 x = x4[d4];
        q4[d4] = e;
        float a = e.x - x.x, b = e.y - x.y, c = e.z - x.z, d = e.w - x.w;
        s += a * a + b * b + c * c + d * d;
    }
    #pragma unroll
    for (int o = 16; o; o >>= 1) s += __shfl_xor_sync(0xffffffffu, s, o);
    if (lane == 0) {
        atomicAdd(&g_diff, (double)s);
        if (write_extra) out[(size_t)NROWS * DIM + 1 + row] = (float)j;
    }
}

__global__ void finalize_kernel(float* __restrict__ out, int write_extra) {
    if (write_extra)
        out[(size_t)NROWS * DIM] = (float)(g_diff * (1.0 / ((double)NROWS * (double)DIM)));
}

// ============================================================
extern "C" void kernel_launch(void* const* d_in, const int* in_sizes, int n_in,
                              void* d_out, int out_size) {
    // Resolve inputs by SIZE (robust to metadata ordering):
    //   input: 8*4096*256 = 8,388,608 elements
    //   embed: 256*8192   = 2,097,152 elements
    const float* input = (const float*)d_in[0];
    const float* embed = (const float*)d_in[1];
    if (in_sizes[0] == NE * DIM && in_sizes[1] == NROWS * DIM) {
        input = (const float*)d_in[1];
        embed = (const float*)d_in[0];
    }
    float* out = (float*)d_out;

    // output layout: [quantize 8388608 | diff 1 | embed_ind 32768]
    int write_extra = (out_size >= NROWS * DIM + 1 + NROWS) ? 1 : 0;

    norms_kernel<<<NE / 256, 256>>>(embed);
    transpose_kernel<<<dim3(NE / 32, DIM / 32), dim3(32, 8)>>>(embed);
    argmin_kernel<<<NROWS / BM, 256>>>(input, embed);
    output_kernel<<<NROWS / 8, 256>>>(input, out, write_extra);
    finalize_kernel<<<1, 1>>>(out, write_extra);
}

// round 5
// speedup vs baseline: 3.3686x; 3.3686x over previous
#include <cuda_runtime.h>
#include <cuda_fp16.h>
#include <cstdint>

#define DIM    256
#define NE     8192
#define NROWS  32768
#define THRESH 0.04f
#define FLAG_CAP NROWS

// ---- device scratch ----
__device__ float  g_c[NE];                 // 0.5*||e_j||^2
__device__ int    g_idx[NROWS];
__device__ float  g_eT[NE * DIM];          // fp32 transposed codebook (gather)
__device__ __half g_epk[NE * DIM];         // fp16 codebook, pre-swizzled k64 slices
__device__ double g_diff;
__device__ int    g_nflag;
__device__ int    g_flag[FLAG_CAP];
__device__ unsigned long long g_rkey[FLAG_CAP];

__device__ __forceinline__ uint32_t smem_u32(const void* p) {
    uint32_t a;
    asm("{ .reg .u64 t; cvta.to.shared.u64 t, %1; cvt.u32.u64 %0, t; }" : "=r"(a) : "l"(p));
    return a;
}

__device__ __forceinline__ void ldmx4(uint32_t& r0, uint32_t& r1, uint32_t& r2, uint32_t& r3,
                                      uint32_t addr) {
    asm volatile("ldmatrix.sync.aligned.m8n8.x4.shared.b16 {%0,%1,%2,%3}, [%4];"
                 : "=r"(r0), "=r"(r1), "=r"(r2), "=r"(r3) : "r"(addr));
}

__device__ __forceinline__ void mma16816(float& c0, float& c1, float& c2, float& c3,
                                         uint32_t a0, uint32_t a1, uint32_t a2, uint32_t a3,
                                         uint32_t b0, uint32_t b1) {
    asm volatile(
        "mma.sync.aligned.m16n8k16.row.col.f32.f16.f16.f32 "
        "{%0,%1,%2,%3}, {%4,%5,%6,%7}, {%8,%9}, {%0,%1,%2,%3};"
        : "+f"(c0), "+f"(c1), "+f"(c2), "+f"(c3)
        : "r"(a0), "r"(a1), "r"(a2), "r"(a3), "r"(b0), "r"(b1));
}

// ============================================================
// Prep kernels
// ============================================================
__global__ void norms_kernel(const float* __restrict__ embed) {
    int j = blockIdx.x * blockDim.x + threadIdx.x;
    if (blockIdx.x == 0 && threadIdx.x == 0) { g_diff = 0.0; g_nflag = 0; }
    if (j < NE) {
        float s = 0.f;
        #pragma unroll 8
        for (int d = 0; d < DIM; ++d) {
            float v = embed[(size_t)d * NE + j];
            s += v * v;
        }
        g_c[j] = 0.5f * s;
    }
}

__global__ void transpose_kernel(const float* __restrict__ embed) {
    __shared__ float t[32][33];
    int j0 = blockIdx.x * 32;
    int d0 = blockIdx.y * 32;
    int tx = threadIdx.x, ty = threadIdx.y;   // 32 x 8
    #pragma unroll
    for (int i = 0; i < 32; i += 8)
        t[ty + i][tx] = embed[(size_t)(d0 + ty + i) * NE + (j0 + tx)];
    __syncthreads();
    #pragma unroll
    for (int i = 0; i < 32; i += 8)
        g_eT[(size_t)(j0 + ty + i) * DIM + (d0 + tx)] = t[tx][ty + i];
}

// Pack codebook into fp16, pre-swizzled k64 slices:
// slice (jt, s): codes [jt*128, +128), dims [s*64, +64)
// layout: halves[(jt*4+s)*8192 + n*64 + swg*8 + (k&7)], swg = ((k>>3)^n)&7
__global__ void pack_kernel(const float* __restrict__ embed) {
    int idx = blockIdx.x * 256 + threadIdx.x;    // over DIM*NE
    int d = idx >> 13;           // / NE
    int j = idx & (NE - 1);
    float v = embed[idx];
    int jt = j >> 7, n = j & 127;
    int s = d >> 6, k = d & 63;
    int swg = ((k >> 3) ^ n) & 7;
    size_t dst = ((size_t)(jt * 4 + s) << 13) + (size_t)n * 64 + swg * 8 + (k & 7);
    g_epk[dst] = __float2half(v);
}

// ============================================================
// Main HMMA kernel: 256 threads, 128 rows per CTA, 256 CTAs.
// A (x rows, fp16) register-resident fragments; B streamed k64 slices.
// ============================================================
__global__ void __launch_bounds__(256, 1)
tc_argmin_kernel(const float* __restrict__ input) {
    __shared__ __align__(16) __half eB[2][8192];  // 2 x 16KB swizzled slices
    __shared__ float cs[128];

    const int tid  = threadIdx.x;
    const int wid  = tid >> 5;
    const int lane = tid & 31;
    const int row0 = blockIdx.x * 128;
    const int mat  = lane >> 3;
    const int rr   = lane & 7;

    const uint32_t eb0 = smem_u32(&eB[0][0]);
    const uint32_t eb1 = smem_u32(&eB[1][0]);

    // ================= prologue: A fragments =================
    // Stage 32 rows at a time into eB[0..] (16KB, swizzled), ldmatrix by 2 warps.
    uint32_t areg[64];   // 16 chunks x 4
    {
        __half* stage = &eB[0][0];
        const int r = tid & 31;     // row within round
        const int p = tid >> 5;     // 32-half segment (0..7)
        #pragma unroll 1
        for (int round = 0; round < 4; ++round) {
            const float4* src = reinterpret_cast<const float4*>(
                input + (size_t)(row0 + round * 32 + r) * DIM + p * 32);
            #pragma unroll
            for (int u = 0; u < 4; ++u) {
                float4 fa = src[u * 2 + 0];
                float4 fb = src[u * 2 + 1];
                __half2 h0 = __floats2half2_rn(fa.x, fa.y);
                __half2 h1 = __floats2half2_rn(fa.z, fa.w);
                __half2 h2 = __floats2half2_rn(fb.x, fb.y);
                __half2 h3 = __floats2half2_rn(fb.z, fb.w);
                uint4 pk;
                pk.x = *reinterpret_cast<uint32_t*>(&h0);
                pk.y = *reinterpret_cast<uint32_t*>(&h1);
                pk.z = *reinterpret_cast<uint32_t*>(&h2);
                pk.w = *reinterpret_cast<uint32_t*>(&h3);
                int g = p * 4 + u;
                int swg = (g & 24) | ((g ^ r) & 7);
                *reinterpret_cast<uint4*>(
                    reinterpret_cast<char*>(stage) + r * 512 + swg * 16) = pk;
            }
            __syncthreads();
            if ((wid >> 1) == round) {
                const int m = (wid & 1) * 16 + (mat & 1) * 8 + rr;
                #pragma unroll
                for (int c = 0; c < 16; ++c) {
                    int g = c * 2 + (mat >> 1);
                    int swg = (g & 24) | ((g ^ rr) & 7);
                    uint32_t addr = smem_u32(stage) + (uint32_t)(m * 512 + swg * 16);
                    ldmx4(areg[c * 4 + 0], areg[c * 4 + 1],
                          areg[c * 4 + 2], areg[c * 4 + 3], addr);
                }
            }
            __syncthreads();
        }
    }

    // ================= main loop =================
    const uint4* epk = reinterpret_cast<const uint4*>(g_epk);

    // initial: cs for tile 0 + slice 0 into eB[0]
    if (tid < 128) cs[tid] = g_c[tid];
    {
        uint4 v0 = epk[tid], v1 = epk[tid + 256], v2 = epk[tid + 512], v3 = epk[tid + 768];
        uint4* dst = reinterpret_cast<uint4*>(&eB[0][0]);
        dst[tid] = v0; dst[tid + 256] = v1; dst[tid + 512] = v2; dst[tid + 768] = v3;
    }
    __syncthreads();

    float creg[64];
    float bb[2] = {-3.0e38f, -3.0e38f};
    float ss[2] = {-3.0e38f, -3.0e38f};
    int   ii[2] = {0, 0};

    // per-lane B address components
    const int hi_n = (mat >> 1) * 8 + rr;
    const int gbit = mat & 1;

    #pragma unroll 1
    for (int t = 0; t < 256; ++t) {
        const int buf = t & 1;
        const uint32_t ebase = buf ? eb1 : eb0;
        const int s = t & 3;

        // 1) prefetch next slice (LDG into regs)
        uint4 v0, v1, v2, v3;
        const bool havenext = (t + 1) < 256;
        if (havenext) {
            const uint4* src = epk + (size_t)(t + 1) * 1024;
            v0 = src[tid]; v1 = src[tid + 256]; v2 = src[tid + 512]; v3 = src[tid + 768];
        }
        float csn = 0.f;
        if (s == 3 && havenext && tid < 128) csn = g_c[((t >> 2) + 1) * 128 + tid];

        // 2) tile start: init C = -0.5||e||^2
        if (s == 0) {
            #pragma unroll
            for (int tl = 0; tl < 16; ++tl) {
                float2 c2 = *reinterpret_cast<const float2*>(&cs[tl * 8 + (lane & 3) * 2]);
                creg[tl * 4 + 0] = -c2.x;
                creg[tl * 4 + 1] = -c2.y;
                creg[tl * 4 + 2] = -c2.x;
                creg[tl * 4 + 3] = -c2.y;
            }
        }

        // 3) compute: 4 k16 chunks x 16 n-tiles
        #pragma unroll
        for (int kc = 0; kc < 4; ++kc) {
            const int ai = (s * 4 + kc) * 4;
            const int swg = ((kc * 2 + gbit) ^ rr) & 7;
            #pragma unroll
            for (int p = 0; p < 8; ++p) {
                uint32_t b0, b1, b2, b3;
                uint32_t addr = ebase + (uint32_t)((p * 16 + hi_n) * 128 + swg * 16);
                ldmx4(b0, b1, b2, b3, addr);
                mma16816(creg[(2*p)*4+0], creg[(2*p)*4+1], creg[(2*p)*4+2], creg[(2*p)*4+3],
                         areg[ai+0], areg[ai+1], areg[ai+2], areg[ai+3], b0, b1);
                mma16816(creg[(2*p+1)*4+0], creg[(2*p+1)*4+1], creg[(2*p+1)*4+2], creg[(2*p+1)*4+3],
                         areg[ai+0], areg[ai+1], areg[ai+2], areg[ai+3], b2, b3);
            }
        }

        // 4) tile end: running top-2 update
        if (s == 3) {
            const int jt = t >> 2;
            #pragma unroll
            for (int tl = 0; tl < 16; ++tl) {
                int n0 = jt * 128 + tl * 8 + (lane & 3) * 2;
                float v;
                v = creg[tl*4+0];
                if (v > bb[0]) { ss[0] = bb[0]; bb[0] = v; ii[0] = n0; }
                else if (v > ss[0]) ss[0] = v;
                v = creg[tl*4+1];
                if (v > bb[0]) { ss[0] = bb[0]; bb[0] = v; ii[0] = n0 + 1; }
                else if (v > ss[0]) ss[0] = v;
                v = creg[tl*4+2];
                if (v > bb[1]) { ss[1] = bb[1]; bb[1] = v; ii[1] = n0; }
                else if (v > ss[1]) ss[1] = v;
                v = creg[tl*4+3];
                if (v > bb[1]) { ss[1] = bb[1]; bb[1] = v; ii[1] = n0 + 1; }
                else if (v > ss[1]) ss[1] = v;
            }
        }

        // 5) store prefetched slice + next cs
        if (havenext) {
            uint4* dst = reinterpret_cast<uint4*>(buf ? &eB[0][0] : &eB[1][0]);
            dst[tid] = v0; dst[tid + 256] = v1; dst[tid + 512] = v2; dst[tid + 768] = v3;
            if (s == 3 && tid < 128) cs[tid] = csn;
        }
        __syncthreads();
    }

    // ================= reduction: quad merge, write =================
    #pragma unroll
    for (int sl = 0; sl < 2; ++sl) {
        float b = bb[sl], sec = ss[sl]; int i = ii[sl];
        #pragma unroll
        for (int off = 1; off <= 2; off <<= 1) {
            float ob = __shfl_xor_sync(0xffffffffu, b, off);
            float os = __shfl_xor_sync(0xffffffffu, sec, off);
            int   oi = __shfl_xor_sync(0xffffffffu, i, off);
            if (ob > b || (ob == b && oi < i)) {
                sec = fmaxf(b, os); b = ob; i = oi;
            } else {
                sec = fmaxf(sec, ob);
            }
        }
        if ((lane & 3) == 0) {
            int row = row0 + wid * 16 + (lane >> 2) + sl * 8;
            g_idx[row] = i;
            if (b - sec < THRESH) {
                int sidx = atomicAdd(&g_nflag, 1);
                if (sidx < FLAG_CAP) { g_flag[sidx] = row; g_rkey[sidx] = 0ull; }
            }
        }
    }
}

// ============================================================
// Exact fp32 rescue for narrow-margin rows.
// ============================================================
__device__ __forceinline__ unsigned long long score_key(float v, int j) {
    uint32_t u = __float_as_uint(v);
    u = (u & 0x80000000u) ? ~u : (u | 0x80000000u);
    return ((unsigned long long)u << 32) | (uint32_t)(0xFFFFFFFFu ^ (uint32_t)j);
}

__global__ void rescue_kernel(const float* __restrict__ input,
                              const float* __restrict__ embed) {
    __shared__ float xs[16][DIM];
    __shared__ unsigned long long wb[8][16];
    int nf = g_nflag; if (nf > FLAG_CAP) nf = FLAG_CAP;
    const int tid = threadIdx.x, wid = tid >> 5, lane = tid & 31;

    for (int base = blockIdx.y * 16; base < nf; base += 16 * 16) {
        int nrows = nf - base; if (nrows > 16) nrows = 16;
        __syncthreads();
        for (int i = tid; i < nrows * DIM; i += 256) {
            int r = i >> 8, d = i & 255;
            xs[r][d] = input[(size_t)g_flag[base + r] * DIM + d];
        }
        __syncthreads();

        int j0 = blockIdx.x * 1024 + tid;     // codes j0 + {0,256,512,768}
        float acc[4][16];
        #pragma unroll
        for (int q = 0; q < 4; ++q)
            #pragma unroll
            for (int r = 0; r < 16; ++r) acc[q][r] = 0.f;

        #pragma unroll 4
        for (int d = 0; d < DIM; ++d) {
            float e0 = embed[(size_t)d * NE + j0];
            float e1 = embed[(size_t)d * NE + j0 + 256];
            float e2 = embed[(size_t)d * NE + j0 + 512];
            float e3 = embed[(size_t)d * NE + j0 + 768];
            #pragma unroll
            for (int r = 0; r < 16; ++r) {
                float x = xs[r][d];
                acc[0][r] += e0 * x;
                acc[1][r] += e1 * x;
                acc[2][r] += e2 * x;
                acc[3][r] += e3 * x;
            }
        }
        float c0 = g_c[j0], c1 = g_c[j0 + 256], c2 = g_c[j0 + 512], c3 = g_c[j0 + 768];

        #pragma unroll 1
        for (int r = 0; r < 16; ++r) {
            float bv = acc[0][r] - c0; int bj = j0;
            float v1 = acc[1][r] - c1; if (v1 > bv) { bv = v1; bj = j0 + 256; }
            float v2 = acc[2][r] - c2; if (v2 > bv) { bv = v2; bj = j0 + 512; }
            float v3 = acc[3][r] - c3; if (v3 > bv) { bv = v3; bj = j0 + 768; }
            unsigned long long key = score_key(bv, bj);
            #pragma unroll
            for (int o = 16; o; o >>= 1) {
                unsigned long long other = __shfl_xor_sync(0xffffffffu, key, o);
                if (other > key) key = other;
            }
            if (lane == 0) wb[wid][r] = key;
        }
        __syncthreads();
        if (tid < nrows) {
            unsigned long long k = wb[0][tid];
            #pragma unroll
            for (int w = 1; w < 8; ++w) if (wb[w][tid] > k) k = wb[w][tid];
            atomicMax(&g_rkey[base + tid], k);
        }
    }
}

__global__ void extract_kernel() {
    int nf = g_nflag; if (nf > FLAG_CAP) nf = FLAG_CAP;
    for (int i = threadIdx.x; i < nf; i += 256) {
        unsigned long long k = g_rkey[i];
        g_idx[g_flag[i]] = (int)(0xFFFFFFFFu ^ (uint32_t)(k & 0xFFFFFFFFull));
    }
}

// ============================================================
// Output: gather, commitment loss, indices.
// ============================================================
__global__ void output_kernel(const float* __restrict__ input,
                              float* __restrict__ out, int write_extra) {
    int row  = blockIdx.x * 8 + (threadIdx.x >> 5);
    int lane = threadIdx.x & 31;
    int j = g_idx[row];
    const float4* x4 = reinterpret_cast<const float4*>(input + (size_t)row * DIM);
    const float4* e4 = reinterpret_cast<const float4*>(g_eT + (size_t)j * DIM);
    float4*       q4 = reinterpret_cast<float4*>(out + (size_t)row * DIM);
    float s = 0.f;
    #pragma unroll
    for (int t = 0; t < 2; ++t) {
        int d4 = lane + t * 32;
        float4 e = e4[d4];
        float4 x = x4[d4];
        q4[d4] = e;
        float a = e.x - x.x, b = e.y - x.y, c = e.z - x.z, d = e.w - x.w;
        s += a * a + b * b + c * c + d * d;
    }
    #pragma unroll
    for (int o = 16; o; o >>= 1) s += __shfl_xor_sync(0xffffffffu, s, o);
    if (lane == 0) {
        atomicAdd(&g_diff, (double)s);
        if (write_extra) out[(size_t)NROWS * DIM + 1 + row] = (float)j;
    }
}

__global__ void finalize_kernel(float* __restrict__ out, int write_extra) {
    if (write_extra)
        out[(size_t)NROWS * DIM] = (float)(g_diff * (1.0 / ((double)NROWS * (double)DIM)));
}

// ============================================================
extern "C" void kernel_launch(void* const* d_in, const int* in_sizes, int n_in,
                              void* d_out, int out_size) {
    const float* input = (const float*)d_in[0];
    const float* embed = (const float*)d_in[1];
    if (in_sizes[0] == NE * DIM && in_sizes[1] == NROWS * DIM) {
        input = (const float*)d_in[1];
        embed = (const float*)d_in[0];
    }
    float* out = (float*)d_out;
    int write_extra = (out_size >= NROWS * DIM + 1 + NROWS) ? 1 : 0;

    norms_kernel<<<NE / 256, 256>>>(embed);
    transpose_kernel<<<dim3(NE / 32, DIM / 32), dim3(32, 8)>>>(embed);
    pack_kernel<<<DIM * NE / 256, 256>>>(embed);
    tc_argmin_kernel<<<NROWS / 128, 256>>>(input);
    rescue_kernel<<<dim3(8, 16), 256>>>(input, embed);
    extract_kernel<<<1, 256>>>();
    output_kernel<<<NROWS / 8, 256>>>(input, out, write_extra);
    finalize_kernel<<<1, 1>>>(out, write_extra);
}